// round 13
// baseline (speedup 1.0000x reference)
#include <cuda_runtime.h>
#include <cuda_fp16.h>
#include <math.h>
#include <stdint.h>

#define D   1024
#define H1  4096
#define H2  4096

// ---------------- scratch (static device globals; no allocation) ----------------
// Chunk-blocked, pre-swizzled fp16 operand layouts:
//   g_W2t[kc][j][64] = rn(W2[j,h]*s[h]),  g_At[kc][i][64] = rn(W1[h,i]);
//   within a row, 16B unit c stored at c^(row&7).
__device__ float   g_s[H1];
__device__ float   g_u0[H1];
__device__ float   g_g[H1];
__device__ float   g_coefQ[H2];
__device__ double  g_acc;
__device__ __half  g_W2t[(size_t)H2 * H1];    // 32 MB
__device__ __half  g_At[(size_t)D * H1];      // 8 MB

// ---------------- portable PTX helpers (sm_90 baseline, no 'a' features) --------
__device__ __forceinline__ uint32_t smem_u32(const void* p) {
    uint32_t a;
    asm("{ .reg .u64 t; cvta.to.shared.u64 t, %1; cvt.u32.u64 %0, t; }" : "=r"(a) : "l"(p));
    return a;
}
#define MBAR_INIT(mb, c) asm volatile("mbarrier.init.shared.b64 [%0], %1;" :: "r"(mb), "r"(c) : "memory")
#define MBAR_EXPECT(mb, n) asm volatile("mbarrier.arrive.expect_tx.shared.b64 _, [%0], %1;" :: "r"(mb), "r"(n) : "memory")
#define BULK_G2S(dst, src, n, mb) \
    asm volatile("cp.async.bulk.shared::cluster.global.mbarrier::complete_tx::bytes [%0], [%1], %2, [%3];" \
                 :: "r"(dst), "l"(src), "r"(n), "r"(mb) : "memory")
__device__ __forceinline__ void mbar_wait(uint32_t mb, uint32_t parity) {
    uint32_t done;
    asm volatile("{ .reg .pred p; mbarrier.try_wait.parity.acquire.cta.shared::cta.b64 p, [%1], %2; selp.b32 %0, 1, 0, p; }"
                 : "=r"(done) : "r"(mb), "r"(parity) : "memory");
    if (!done) {
        asm volatile("{ .reg .pred P1; WL%=: mbarrier.try_wait.parity.acquire.cta.shared::cta.b64 P1, [%0], %1, 0x989680; @P1 bra.uni WD%=; bra.uni WL%=; WD%=: }"
                     :: "r"(mb), "r"(parity) : "memory");
    }
}
__device__ __forceinline__ void ldm4(uint32_t addr, uint32_t r[4]) {
    asm volatile("ldmatrix.sync.aligned.m8n8.x4.shared.b16 {%0,%1,%2,%3}, [%4];"
                 : "=r"(r[0]), "=r"(r[1]), "=r"(r[2]), "=r"(r[3]) : "r"(addr));
}
// fp16-accumulator MMA: D,C packed half2 pairs {c0c1, c2c3}
__device__ __forceinline__ void mma16816h(uint32_t c[2], const uint32_t a[4],
                                          uint32_t b0, uint32_t b1) {
    asm volatile("mma.sync.aligned.m16n8k16.row.col.f16.f16.f16.f16 "
                 "{%0,%1}, {%2,%3,%4,%5}, {%6,%7}, {%0,%1};"
                 : "+r"(c[0]), "+r"(c[1])
                 : "r"(a[0]), "r"(a[1]), "r"(a[2]), "r"(a[3]), "r"(b0), "r"(b1));
}
__device__ __forceinline__ float wred(float v) {
    #pragma unroll
    for (int o = 16; o > 0; o >>= 1)
        v += __shfl_xor_sync(0xFFFFFFFFu, v, o);
    return v;
}
__device__ __forceinline__ uint32_t packh2(float a, float b) {
    return (uint32_t)__half_as_ushort(__float2half_rn(a))
         | ((uint32_t)__half_as_ushort(__float2half_rn(b)) << 16);
}

// ---------------- K1: layer-1, warp per row (+ g_acc init) ----------------
__global__ __launch_bounds__(256) void k_layer1(const float* __restrict__ W1,
                                                const float* __restrict__ x,
                                                const float* __restrict__ b1) {
    if (blockIdx.x == 0 && threadIdx.x == 0) g_acc = 0.0;
    int wid  = threadIdx.x >> 5;
    int lane = threadIdx.x & 31;
    int h    = blockIdx.x * 8 + wid;
    const float4* W4 = reinterpret_cast<const float4*>(W1 + (size_t)h * D);
    const float4* x4 = reinterpret_cast<const float4*>(x);
    float dot = 0.f, r = 0.f;
    #pragma unroll
    for (int q = 0; q < 8; q++) {
        float4 w  = W4[lane + q * 32];
        float4 xv = x4[lane + q * 32];
        dot += w.x * xv.x + w.y * xv.y + w.z * xv.z + w.w * xv.w;
        r   += w.x * w.x  + w.y * w.y  + w.z * w.z  + w.w * w.w;
    }
    dot = wred(dot);
    r   = wred(r);
    if (lane == 0) {
        float u0 = tanhf(dot + b1[h]);
        float s  = 1.0f - u0 * u0;
        g_s[h]   = s;
        g_u0[h]  = u0;
        g_g[h]   = -2.0f * u0 * s * r;
    }
}

// ---------------- K_T: transpose W1 -> fp16, chunk-blocked+swizzled --------------
__global__ __launch_bounds__(256) void k_transpose(const float* __restrict__ W1) {
    __shared__ float tile[64][33];
    int i0 = blockIdx.x * 32;
    int h0 = blockIdx.y * 64;
    int t  = threadIdx.x;
    {
        int c = t & 31;
        int rbase = (t >> 5) * 8;
        #pragma unroll
        for (int q = 0; q < 8; q++)
            tile[rbase + q][c] = W1[(size_t)(h0 + rbase + q) * D + i0 + c];
    }
    __syncthreads();
    int il = t >> 3;
    int c  = t & 7;
    int i  = i0 + il;
    uint4 o;
    o.x = packh2(tile[c * 8 + 0][il], tile[c * 8 + 1][il]);
    o.y = packh2(tile[c * 8 + 2][il], tile[c * 8 + 3][il]);
    o.z = packh2(tile[c * 8 + 4][il], tile[c * 8 + 5][il]);
    o.w = packh2(tile[c * 8 + 6][il], tile[c * 8 + 7][il]);
    size_t off = ((size_t)(h0 >> 6) * D + i) * 64 + ((c ^ (i & 7)) << 3);
    *reinterpret_cast<uint4*>(g_At + off) = o;
}

// ---------------- K2: layer-2, 4 rows per block; W2t = rn(W2*s) fp16 -------------
__global__ __launch_bounds__(256) void k_layer2(const float* __restrict__ W2,
                                                const float* __restrict__ b2,
                                                const float* __restrict__ W3) {
    int j0 = blockIdx.x * 4;
    int t  = threadIdx.x;
    const float4* u4 = reinterpret_cast<const float4*>(g_u0);
    const float4* g4 = reinterpret_cast<const float4*>(g_g);
    const float4* s4 = reinterpret_cast<const float4*>(g_s);
    float z0[4]  = {0.f, 0.f, 0.f, 0.f};
    float sz2[4] = {0.f, 0.f, 0.f, 0.f};
    #pragma unroll
    for (int q = 0; q < 2; q++) {
        int u = t + q * 256;
        float4 ua = u4[u * 2], ub = u4[u * 2 + 1];
        float4 ga = g4[u * 2], gb = g4[u * 2 + 1];
        float4 sa = s4[u * 2], sb = s4[u * 2 + 1];
        #pragma unroll
        for (int r = 0; r < 4; r++) {
            int j = j0 + r;
            const float4* W4 = reinterpret_cast<const float4*>(W2 + (size_t)j * H1);
            float4 w0 = W4[u * 2];
            float4 w1 = W4[u * 2 + 1];
            z0[r]  += w0.x * ua.x + w0.y * ua.y + w0.z * ua.z + w0.w * ua.w
                    + w1.x * ub.x + w1.y * ub.y + w1.z * ub.z + w1.w * ub.w;
            sz2[r] += w0.x * ga.x + w0.y * ga.y + w0.z * ga.z + w0.w * ga.w
                    + w1.x * gb.x + w1.y * gb.y + w1.z * gb.z + w1.w * gb.w;
            uint4 o;
            o.x = packh2(w0.x * sa.x, w0.y * sa.y);
            o.y = packh2(w0.z * sa.z, w0.w * sa.w);
            o.z = packh2(w1.x * sb.x, w1.y * sb.y);
            o.w = packh2(w1.z * sb.z, w1.w * sb.w);
            size_t off = ((size_t)(u >> 3) * H2 + j) * 64 + (((u & 7) ^ (j & 7)) << 3);
            *reinterpret_cast<uint4*>(g_W2t + off) = o;
        }
    }
    #pragma unroll
    for (int r = 0; r < 4; r++) { z0[r] = wred(z0[r]); sz2[r] = wred(sz2[r]); }
    __shared__ float pz[4][8], ps[4][8];
    int wid = t >> 5, lane = t & 31;
    if (lane == 0) {
        #pragma unroll
        for (int r = 0; r < 4; r++) { pz[r][wid] = z0[r]; ps[r][wid] = sz2[r]; }
    }
    __syncthreads();
    if (t < 4) {
        float a = 0.f, b = 0.f;
        #pragma unroll
        for (int q = 0; q < 8; q++) { a += pz[t][q]; b += ps[t][q]; }
        int j = j0 + t;
        float v0 = tanhf(a + b2[j]);
        float tt = 1.0f - v0 * v0;
        float w3 = W3[j];
        atomicAdd(&g_acc, (double)(w3 * tt * b));
        g_coefQ[j] = -2.0f * w3 * v0 * tt;
    }
}

// ---------------- K3: fp16-acc mma.sync GEMM + per-chunk fp32 promotion ----------
// Block 128x128, BK=64, 8 warps (32x64 warp tile), 3-stage bulk-copy.
// Chunk accumulates in fp16 (4 chained MMAs); flushed to fp32 each chunk.
#define BK        64
#define NCH       (H1 / BK)          // 64
#define TILE_BY   16384
#define STAGE_BY  (2 * TILE_BY)      // 32 KB
#define GEMM_SMEM (1024 + 1024 + 3 * STAGE_BY)

__global__ __launch_bounds__(256, 2) void k_gemm() {
    extern __shared__ char dyn[];
    uint32_t raw  = smem_u32(dyn);
    uint32_t base = (raw + 1023u) & ~1023u;
    char*    gen  = dyn + (base - raw);
    const uint32_t stage0 = base + 1024;

    const int t    = threadIdx.x;
    const int w    = t >> 5;
    const int lane = t & 31;
    const int j0   = blockIdx.x * 128;
    const int i0   = blockIdx.y * 128;

    if (t == 0) {
        MBAR_INIT(base + 0, 1);
        MBAR_INIT(base + 8, 1);
        MBAR_INIT(base + 16, 1);
    }
    __syncthreads();

    const char* srcA = (const char*)g_W2t + (size_t)j0 * 128;
    const char* srcB = (const char*)g_At  + (size_t)i0 * 128;

    auto issue = [&](int s, int kc) {
        uint32_t mb = base + 8u * (uint32_t)s;
        uint32_t db = stage0 + (uint32_t)s * STAGE_BY;
        MBAR_EXPECT(mb, (uint32_t)STAGE_BY);
        BULK_G2S(db,           srcA + (size_t)kc * H2 * 128, (uint32_t)TILE_BY, mb);
        BULK_G2S(db + TILE_BY, srcB + (size_t)kc * D  * 128, (uint32_t)TILE_BY, mb);
    };

    const int m0 = (w >> 1) * 32;
    const int n0 = (w & 1) * 64;
    const uint32_t sw   = (uint32_t)(lane & 7);
    const uint32_t rsel = (uint32_t)(lane >> 4);
    uint32_t aRow[2], bRow[4];
    #pragma unroll
    for (int mt = 0; mt < 2; mt++)
        aRow[mt] = stage0 + (uint32_t)((m0 + 16 * mt + (lane & 15)) * 128);
    #pragma unroll
    for (int bt = 0; bt < 4; bt++)
        bRow[bt] = stage0 + TILE_BY + (uint32_t)((n0 + 16 * bt + (lane & 15)) * 128);

    float    facc[2][8][4];
    uint32_t hacc[2][8][2];
    #pragma unroll
    for (int mt = 0; mt < 2; mt++)
        #pragma unroll
        for (int nt = 0; nt < 8; nt++) {
            #pragma unroll
            for (int e = 0; e < 4; e++) facc[mt][nt][e] = 0.f;
            hacc[mt][nt][0] = 0u;
            hacc[mt][nt][1] = 0u;
        }

    if (t == 0) { issue(0, 0); issue(1, 1); }

    int st = 0, ld = 2;
    uint32_t phase[3] = {0u, 0u, 0u};
    #pragma unroll 1
    for (int k = 0; k < NCH; k++) {
        __syncthreads();
        if (t == 0 && k + 2 < NCH) issue(ld, k + 2);
        mbar_wait(base + 8u * (uint32_t)st, phase[st]);
        phase[st] ^= 1u;
        const uint32_t sb = (uint32_t)st * STAGE_BY;
        #pragma unroll
        for (int ks = 0; ks < 4; ks++) {
            const uint32_t off = (((2u * ks + rsel) ^ sw) << 4) + sb;
            uint32_t ah0[4], ah1[4];
            ldm4(aRow[0] + off, ah0);
            ldm4(aRow[1] + off, ah1);
            #pragma unroll
            for (int hb = 0; hb < 2; hb++) {
                uint32_t b0[4], b1[4];
                ldm4(bRow[hb * 2 + 0] + off, b0);
                ldm4(bRow[hb * 2 + 1] + off, b1);
                mma16816h(hacc[0][hb * 4 + 0], ah0, b0[0], b0[2]);
                mma16816h(hacc[0][hb * 4 + 1], ah0, b0[1], b0[3]);
                mma16816h(hacc[1][hb * 4 + 0], ah1, b0[0], b0[2]);
                mma16816h(hacc[1][hb * 4 + 1], ah1, b0[1], b0[3]);
                mma16816h(hacc[0][hb * 4 + 2], ah0, b1[0], b1[2]);
                mma16816h(hacc[0][hb * 4 + 3], ah0, b1[1], b1[3]);
                mma16816h(hacc[1][hb * 4 + 2], ah1, b1[0], b1[2]);
                mma16816h(hacc[1][hb * 4 + 3], ah1, b1[1], b1[3]);
            }
        }
        // flush fp16 chunk accumulators into fp32
        #pragma unroll
        for (int mt = 0; mt < 2; mt++)
            #pragma unroll
            for (int nt = 0; nt < 8; nt++) {
                float2 lo = __half22float2(*reinterpret_cast<__half2*>(&hacc[mt][nt][0]));
                float2 hi = __half22float2(*reinterpret_cast<__half2*>(&hacc[mt][nt][1]));
                facc[mt][nt][0] += lo.x;
                facc[mt][nt][1] += lo.y;
                facc[mt][nt][2] += hi.x;
                facc[mt][nt][3] += hi.y;
                hacc[mt][nt][0] = 0u;
                hacc[mt][nt][1] = 0u;
            }
        st = (st == 2) ? 0 : st + 1;
        ld = (ld == 2) ? 0 : ld + 1;
    }

    // epilogue
    float part = 0.f;
    #pragma unroll
    for (int mt = 0; mt < 2; mt++) {
        int r0 = j0 + m0 + 16 * mt + (lane >> 2);
        float c0 = g_coefQ[r0];
        float c1 = g_coefQ[r0 + 8];
        float s0 = 0.f, s1 = 0.f;
        #pragma unroll
        for (int nt = 0; nt < 8; nt++) {
            s0 = fmaf(facc[mt][nt][0], facc[mt][nt][0], s0);
            s0 = fmaf(facc[mt][nt][1], facc[mt][nt][1], s0);
            s1 = fmaf(facc[mt][nt][2], facc[mt][nt][2], s1);
            s1 = fmaf(facc[mt][nt][3], facc[mt][nt][3], s1);
        }
        part = fmaf(c0, s0, part);
        part = fmaf(c1, s1, part);
    }
    part += __shfl_xor_sync(0xFFFFFFFFu, part, 16);
    part += __shfl_xor_sync(0xFFFFFFFFu, part, 8);
    part += __shfl_xor_sync(0xFFFFFFFFu, part, 4);
    part += __shfl_xor_sync(0xFFFFFFFFu, part, 2);
    part += __shfl_xor_sync(0xFFFFFFFFu, part, 1);
    __syncthreads();
    float* red = reinterpret_cast<float*>(gen);
    if (lane == 0) red[w] = part;
    __syncthreads();
    if (t == 0) {
        float s = 0.f;
        #pragma unroll
        for (int q = 0; q < 8; q++) s += red[q];
        atomicAdd(&g_acc, (double)s);
    }
}

// ---------------- finalize ----------------
__global__ void k_final(float* __restrict__ out) { out[0] = (float)g_acc; }

// ---------------- launch ----------------
extern "C" void kernel_launch(void* const* d_in, const int* in_sizes, int n_in,
                              void* d_out, int out_size) {
    const float* x  = (const float*)d_in[0];
    const float* W1 = (const float*)d_in[1];
    const float* b1 = (const float*)d_in[2];
    const float* W2 = (const float*)d_in[3];
    const float* b2 = (const float*)d_in[4];
    const float* W3 = (const float*)d_in[5];
    float* out = (float*)d_out;

    cudaFuncSetAttribute(k_gemm, cudaFuncAttributeMaxDynamicSharedMemorySize, GEMM_SMEM);

    k_layer1<<<H1 / 8, 256>>>(W1, x, b1);
    k_transpose<<<dim3(D / 32, H1 / 64), 256>>>(W1);
    k_layer2<<<H2 / 4, 256>>>(W2, b2, W3);
    k_gemm<<<dim3(H2 / 128, D / 128), 256, GEMM_SMEM>>>();
    k_final<<<1, 1>>>(out);
}

// round 14
// speedup vs baseline: 1.0447x; 1.0447x over previous
#include <cuda_runtime.h>
#include <cuda_fp16.h>
#include <math.h>
#include <stdint.h>

#define D   1024
#define H1  4096
#define H2  4096

// ---------------- scratch (static device globals; no allocation) ----------------
// Chunk-blocked, pre-swizzled fp16 operand layouts:
//   g_W2t[kc][j][64] = rn(W2[j,h]*s[h]),  g_At[kc][i][64] = rn(W1[h,i]);
//   within a row, 16B unit c stored at c^(row&7).
__device__ float   g_s[H1];
__device__ float   g_u0[H1];
__device__ float   g_g[H1];
__device__ float   g_coefQ[H2];
__device__ double  g_acc;
__device__ __half  g_W2t[(size_t)H2 * H1];    // 32 MB
__device__ __half  g_At[(size_t)D * H1];      // 8 MB

// ---------------- portable PTX helpers (sm_90 baseline, no 'a' features) --------
__device__ __forceinline__ uint32_t smem_u32(const void* p) {
    uint32_t a;
    asm("{ .reg .u64 t; cvta.to.shared.u64 t, %1; cvt.u32.u64 %0, t; }" : "=r"(a) : "l"(p));
    return a;
}
#define MBAR_INIT(mb, c) asm volatile("mbarrier.init.shared.b64 [%0], %1;" :: "r"(mb), "r"(c) : "memory")
#define MBAR_EXPECT(mb, n) asm volatile("mbarrier.arrive.expect_tx.shared.b64 _, [%0], %1;" :: "r"(mb), "r"(n) : "memory")
#define BULK_G2S(dst, src, n, mb) \
    asm volatile("cp.async.bulk.shared::cluster.global.mbarrier::complete_tx::bytes [%0], [%1], %2, [%3];" \
                 :: "r"(dst), "l"(src), "r"(n), "r"(mb) : "memory")
__device__ __forceinline__ void mbar_wait(uint32_t mb, uint32_t parity) {
    uint32_t done;
    asm volatile("{ .reg .pred p; mbarrier.try_wait.parity.acquire.cta.shared::cta.b64 p, [%1], %2; selp.b32 %0, 1, 0, p; }"
                 : "=r"(done) : "r"(mb), "r"(parity) : "memory");
    if (!done) {
        asm volatile("{ .reg .pred P1; WL%=: mbarrier.try_wait.parity.acquire.cta.shared::cta.b64 P1, [%0], %1, 0x989680; @P1 bra.uni WD%=; bra.uni WL%=; WD%=: }"
                     :: "r"(mb), "r"(parity) : "memory");
    }
}
__device__ __forceinline__ void ldm4(uint32_t addr, uint32_t r[4]) {
    asm volatile("ldmatrix.sync.aligned.m8n8.x4.shared.b16 {%0,%1,%2,%3}, [%4];"
                 : "=r"(r[0]), "=r"(r[1]), "=r"(r[2]), "=r"(r[3]) : "r"(addr));
}
__device__ __forceinline__ void mma16816(float c[4], const uint32_t a[4],
                                         uint32_t b0, uint32_t b1) {
    asm volatile("mma.sync.aligned.m16n8k16.row.col.f32.f16.f16.f32 "
                 "{%0,%1,%2,%3}, {%4,%5,%6,%7}, {%8,%9}, {%0,%1,%2,%3};"
                 : "+f"(c[0]), "+f"(c[1]), "+f"(c[2]), "+f"(c[3])
                 : "r"(a[0]), "r"(a[1]), "r"(a[2]), "r"(a[3]), "r"(b0), "r"(b1));
}
__device__ __forceinline__ float wred(float v) {
    #pragma unroll
    for (int o = 16; o > 0; o >>= 1)
        v += __shfl_xor_sync(0xFFFFFFFFu, v, o);
    return v;
}
__device__ __forceinline__ uint32_t packh2(float a, float b) {
    return (uint32_t)__half_as_ushort(__float2half_rn(a))
         | ((uint32_t)__half_as_ushort(__float2half_rn(b)) << 16);
}

// ---------------- K1: layer-1, warp per row (+ g_acc init) ----------------
__global__ __launch_bounds__(256) void k_layer1(const float* __restrict__ W1,
                                                const float* __restrict__ x,
                                                const float* __restrict__ b1) {
    if (blockIdx.x == 0 && threadIdx.x == 0) g_acc = 0.0;
    int wid  = threadIdx.x >> 5;
    int lane = threadIdx.x & 31;
    int h    = blockIdx.x * 8 + wid;
    const float4* W4 = reinterpret_cast<const float4*>(W1 + (size_t)h * D);
    const float4* x4 = reinterpret_cast<const float4*>(x);
    float dot = 0.f, r = 0.f;
    #pragma unroll
    for (int q = 0; q < 8; q++) {
        float4 w  = W4[lane + q * 32];
        float4 xv = x4[lane + q * 32];
        dot += w.x * xv.x + w.y * xv.y + w.z * xv.z + w.w * xv.w;
        r   += w.x * w.x  + w.y * w.y  + w.z * w.z  + w.w * w.w;
    }
    dot = wred(dot);
    r   = wred(r);
    if (lane == 0) {
        float u0 = tanhf(dot + b1[h]);
        float s  = 1.0f - u0 * u0;
        g_s[h]   = s;
        g_u0[h]  = u0;
        g_g[h]   = -2.0f * u0 * s * r;
    }
}

// ---------------- K_T: transpose W1 -> fp16, chunk-blocked+swizzled --------------
__global__ __launch_bounds__(256) void k_transpose(const float* __restrict__ W1) {
    __shared__ float tile[64][33];
    int i0 = blockIdx.x * 32;
    int h0 = blockIdx.y * 64;
    int t  = threadIdx.x;
    {
        int c = t & 31;
        int rbase = (t >> 5) * 8;
        #pragma unroll
        for (int q = 0; q < 8; q++)
            tile[rbase + q][c] = W1[(size_t)(h0 + rbase + q) * D + i0 + c];
    }
    __syncthreads();
    int il = t >> 3;
    int c  = t & 7;
    int i  = i0 + il;
    uint4 o;
    o.x = packh2(tile[c * 8 + 0][il], tile[c * 8 + 1][il]);
    o.y = packh2(tile[c * 8 + 2][il], tile[c * 8 + 3][il]);
    o.z = packh2(tile[c * 8 + 4][il], tile[c * 8 + 5][il]);
    o.w = packh2(tile[c * 8 + 6][il], tile[c * 8 + 7][il]);
    size_t off = ((size_t)(h0 >> 6) * D + i) * 64 + ((c ^ (i & 7)) << 3);
    *reinterpret_cast<uint4*>(g_At + off) = o;
}

// ---------------- K2: layer-2, 4 rows per block; W2t = rn(W2*s) fp16 -------------
__global__ __launch_bounds__(256) void k_layer2(const float* __restrict__ W2,
                                                const float* __restrict__ b2,
                                                const float* __restrict__ W3) {
    int j0 = blockIdx.x * 4;
    int t  = threadIdx.x;
    const float4* u4 = reinterpret_cast<const float4*>(g_u0);
    const float4* g4 = reinterpret_cast<const float4*>(g_g);
    const float4* s4 = reinterpret_cast<const float4*>(g_s);
    float z0[4]  = {0.f, 0.f, 0.f, 0.f};
    float sz2[4] = {0.f, 0.f, 0.f, 0.f};
    #pragma unroll
    for (int q = 0; q < 2; q++) {
        int u = t + q * 256;
        float4 ua = u4[u * 2], ub = u4[u * 2 + 1];
        float4 ga = g4[u * 2], gb = g4[u * 2 + 1];
        float4 sa = s4[u * 2], sb = s4[u * 2 + 1];
        #pragma unroll
        for (int r = 0; r < 4; r++) {
            int j = j0 + r;
            const float4* W4 = reinterpret_cast<const float4*>(W2 + (size_t)j * H1);
            float4 w0 = W4[u * 2];
            float4 w1 = W4[u * 2 + 1];
            z0[r]  += w0.x * ua.x + w0.y * ua.y + w0.z * ua.z + w0.w * ua.w
                    + w1.x * ub.x + w1.y * ub.y + w1.z * ub.z + w1.w * ub.w;
            sz2[r] += w0.x * ga.x + w0.y * ga.y + w0.z * ga.z + w0.w * ga.w
                    + w1.x * gb.x + w1.y * gb.y + w1.z * gb.z + w1.w * gb.w;
            uint4 o;
            o.x = packh2(w0.x * sa.x, w0.y * sa.y);
            o.y = packh2(w0.z * sa.z, w0.w * sa.w);
            o.z = packh2(w1.x * sb.x, w1.y * sb.y);
            o.w = packh2(w1.z * sb.z, w1.w * sb.w);
            size_t off = ((size_t)(u >> 3) * H2 + j) * 64 + (((u & 7) ^ (j & 7)) << 3);
            *reinterpret_cast<uint4*>(g_W2t + off) = o;
        }
    }
    #pragma unroll
    for (int r = 0; r < 4; r++) { z0[r] = wred(z0[r]); sz2[r] = wred(sz2[r]); }
    __shared__ float pz[4][8], ps[4][8];
    int wid = t >> 5, lane = t & 31;
    if (lane == 0) {
        #pragma unroll
        for (int r = 0; r < 4; r++) { pz[r][wid] = z0[r]; ps[r][wid] = sz2[r]; }
    }
    __syncthreads();
    if (t < 4) {
        float a = 0.f, b = 0.f;
        #pragma unroll
        for (int q = 0; q < 8; q++) { a += pz[t][q]; b += ps[t][q]; }
        int j = j0 + t;
        float v0 = tanhf(a + b2[j]);
        float tt = 1.0f - v0 * v0;
        float w3 = W3[j];
        atomicAdd(&g_acc, (double)(w3 * tt * b));
        g_coefQ[j] = -2.0f * w3 * v0 * tt;
    }
}

// ---------------- K3: fp16 mma.sync GEMM, 128x64 tile, 3 CTA/SM ------------------
// z1[j,i] = sum_h rn(W2*s)[j,h] * rn(W1^T)[i,h];  acc += coefQ[j]*z1^2
// Block 128(j) x 64(i), BK=64, 8 warps (warp tile 32x32), 3-stage bulk-copy.
// 512 CTAs; 3 CTAs/SM => 6 warps/SMSP for MMA supply.
#define BK        64
#define NCH       (H1 / BK)          // 64
#define TILE_A_BY 16384              // 128 rows * 128B
#define TILE_B_BY 8192               // 64 rows * 128B
#define STAGE_BY  (TILE_A_BY + TILE_B_BY)  // 24 KB
#define GEMM_SMEM (1024 + 1024 + 3 * STAGE_BY)

__global__ __launch_bounds__(256, 3) void k_gemm() {
    extern __shared__ char dyn[];
    uint32_t raw  = smem_u32(dyn);
    uint32_t base = (raw + 1023u) & ~1023u;
    char*    gen  = dyn + (base - raw);
    const uint32_t stage0 = base + 1024;

    const int t    = threadIdx.x;
    const int w    = t >> 5;
    const int lane = t & 31;
    const int j0   = blockIdx.x * 128;
    const int i0   = blockIdx.y * 64;

    if (t == 0) {
        MBAR_INIT(base + 0, 1);
        MBAR_INIT(base + 8, 1);
        MBAR_INIT(base + 16, 1);
    }
    __syncthreads();

    const char* srcA = (const char*)g_W2t + (size_t)j0 * 128;
    const char* srcB = (const char*)g_At  + (size_t)i0 * 128;

    auto issue = [&](int s, int kc) {
        uint32_t mb = base + 8u * (uint32_t)s;
        uint32_t db = stage0 + (uint32_t)s * STAGE_BY;
        MBAR_EXPECT(mb, (uint32_t)STAGE_BY);
        BULK_G2S(db,             srcA + (size_t)kc * H2 * 128, (uint32_t)TILE_A_BY, mb);
        BULK_G2S(db + TILE_A_BY, srcB + (size_t)kc * D  * 128, (uint32_t)TILE_B_BY, mb);
    };

    // warp tiling: 32(m) x 32(n); m0 = (w>>1)*32, n0 = (w&1)*32
    const int m0 = (w >> 1) * 32;
    const int n0 = (w & 1) * 32;
    const uint32_t sw   = (uint32_t)(lane & 7);
    const uint32_t rsel = (uint32_t)(lane >> 4);
    uint32_t aRow[2], bRow[2];
    #pragma unroll
    for (int mt = 0; mt < 2; mt++)
        aRow[mt] = stage0 + (uint32_t)((m0 + 16 * mt + (lane & 15)) * 128);
    #pragma unroll
    for (int bt = 0; bt < 2; bt++)
        bRow[bt] = stage0 + TILE_A_BY + (uint32_t)((n0 + 16 * bt + (lane & 15)) * 128);

    float acc[2][4][4];
    #pragma unroll
    for (int mt = 0; mt < 2; mt++)
        #pragma unroll
        for (int nt = 0; nt < 4; nt++)
            #pragma unroll
            for (int e = 0; e < 4; e++) acc[mt][nt][e] = 0.f;

    if (t == 0) { issue(0, 0); issue(1, 1); }

    int st = 0, ld = 2;
    uint32_t phase[3] = {0u, 0u, 0u};
    #pragma unroll 1
    for (int k = 0; k < NCH; k++) {
        __syncthreads();                       // stage 'ld' fully consumed
        if (t == 0 && k + 2 < NCH) issue(ld, k + 2);
        mbar_wait(base + 8u * (uint32_t)st, phase[st]);
        phase[st] ^= 1u;
        const uint32_t sb = (uint32_t)st * STAGE_BY;
        #pragma unroll
        for (int ks = 0; ks < 4; ks++) {
            const uint32_t off = (((2u * ks + rsel) ^ sw) << 4) + sb;
            uint32_t ah0[4], ah1[4], b0[4], b1[4];
            ldm4(aRow[0] + off, ah0);
            ldm4(aRow[1] + off, ah1);
            ldm4(bRow[0] + off, b0);
            ldm4(bRow[1] + off, b1);
            mma16816(acc[0][0], ah0, b0[0], b0[2]);
            mma16816(acc[0][1], ah0, b0[1], b0[3]);
            mma16816(acc[1][0], ah1, b0[0], b0[2]);
            mma16816(acc[1][1], ah1, b0[1], b0[3]);
            mma16816(acc[0][2], ah0, b1[0], b1[2]);
            mma16816(acc[0][3], ah0, b1[1], b1[3]);
            mma16816(acc[1][2], ah1, b1[0], b1[2]);
            mma16816(acc[1][3], ah1, b1[1], b1[3]);
        }
        st = (st == 2) ? 0 : st + 1;
        ld = (ld == 2) ? 0 : ld + 1;
    }

    // epilogue
    float part = 0.f;
    #pragma unroll
    for (int mt = 0; mt < 2; mt++) {
        int r0 = j0 + m0 + 16 * mt + (lane >> 2);
        float c0 = g_coefQ[r0];
        float c1 = g_coefQ[r0 + 8];
        float s0 = 0.f, s1 = 0.f;
        #pragma unroll
        for (int nt = 0; nt < 4; nt++) {
            s0 = fmaf(acc[mt][nt][0], acc[mt][nt][0], s0);
            s0 = fmaf(acc[mt][nt][1], acc[mt][nt][1], s0);
            s1 = fmaf(acc[mt][nt][2], acc[mt][nt][2], s1);
            s1 = fmaf(acc[mt][nt][3], acc[mt][nt][3], s1);
        }
        part = fmaf(c0, s0, part);
        part = fmaf(c1, s1, part);
    }
    part += __shfl_xor_sync(0xFFFFFFFFu, part, 16);
    part += __shfl_xor_sync(0xFFFFFFFFu, part, 8);
    part += __shfl_xor_sync(0xFFFFFFFFu, part, 4);
    part += __shfl_xor_sync(0xFFFFFFFFu, part, 2);
    part += __shfl_xor_sync(0xFFFFFFFFu, part, 1);
    __syncthreads();
    float* red = reinterpret_cast<float*>(gen);
    if (lane == 0) red[w] = part;
    __syncthreads();
    if (t == 0) {
        float s = 0.f;
        #pragma unroll
        for (int q = 0; q < 8; q++) s += red[q];
        atomicAdd(&g_acc, (double)s);
    }
}

// ---------------- finalize ----------------
__global__ void k_final(float* __restrict__ out) { out[0] = (float)g_acc; }

// ---------------- launch ----------------
extern "C" void kernel_launch(void* const* d_in, const int* in_sizes, int n_in,
                              void* d_out, int out_size) {
    const float* x  = (const float*)d_in[0];
    const float* W1 = (const float*)d_in[1];
    const float* b1 = (const float*)d_in[2];
    const float* W2 = (const float*)d_in[3];
    const float* b2 = (const float*)d_in[4];
    const float* W3 = (const float*)d_in[5];
    float* out = (float*)d_out;

    cudaFuncSetAttribute(k_gemm, cudaFuncAttributeMaxDynamicSharedMemorySize, GEMM_SMEM);

    k_layer1<<<H1 / 8, 256>>>(W1, x, b1);
    k_transpose<<<dim3(D / 32, H1 / 64), 256>>>(W1);
    k_layer2<<<H2 / 4, 256>>>(W2, b2, W3);
    k_gemm<<<dim3(H2 / 128, D / 64), 256, GEMM_SMEM>>>();
    k_final<<<1, 1>>>(out);
}

// round 16
// speedup vs baseline: 1.1273x; 1.0791x over previous
#include <cuda_runtime.h>
#include <cuda_fp16.h>
#include <math.h>
#include <stdint.h>

#define D   1024
#define H1  4096
#define H2  4096

// ---------------- scratch (static device globals; no allocation) ----------------
// Chunk-blocked, pre-swizzled fp16 operand layouts:
//   g_W2t[kc][j][64] = rn(W2[j,h]*s[h]),  g_At[kc][i][64] = rn(W1[h,i]);
//   within a row, 16B unit c stored at c^(row&7).
__device__ float   g_s[H1];
__device__ float   g_u0[H1];
__device__ float   g_g[H1];
__device__ float   g_coefQ[H2];
__device__ double  g_acc;
__device__ __half  g_W2t[(size_t)H2 * H1];    // 32 MB
__device__ __half  g_At[(size_t)D * H1];      // 8 MB

// ---------------- portable PTX helpers (sm_90 baseline, no 'a' features) --------
__device__ __forceinline__ uint32_t smem_u32(const void* p) {
    uint32_t a;
    asm("{ .reg .u64 t; cvta.to.shared.u64 t, %1; cvt.u32.u64 %0, t; }" : "=r"(a) : "l"(p));
    return a;
}
#define MBAR_INIT(mb, c) asm volatile("mbarrier.init.shared.b64 [%0], %1;" :: "r"(mb), "r"(c) : "memory")
#define MBAR_EXPECT(mb, n) asm volatile("mbarrier.arrive.expect_tx.shared.b64 _, [%0], %1;" :: "r"(mb), "r"(n) : "memory")
#define BULK_G2S(dst, src, n, mb) \
    asm volatile("cp.async.bulk.shared::cluster.global.mbarrier::complete_tx::bytes [%0], [%1], %2, [%3];" \
                 :: "r"(dst), "l"(src), "r"(n), "r"(mb) : "memory")
__device__ __forceinline__ void mbar_wait(uint32_t mb, uint32_t parity) {
    uint32_t done;
    asm volatile("{ .reg .pred p; mbarrier.try_wait.parity.acquire.cta.shared::cta.b64 p, [%1], %2; selp.b32 %0, 1, 0, p; }"
                 : "=r"(done) : "r"(mb), "r"(parity) : "memory");
    if (!done) {
        asm volatile("{ .reg .pred P1; WL%=: mbarrier.try_wait.parity.acquire.cta.shared::cta.b64 P1, [%0], %1, 0x989680; @P1 bra.uni WD%=; bra.uni WL%=; WD%=: }"
                     :: "r"(mb), "r"(parity) : "memory");
    }
}
__device__ __forceinline__ void ldm4(uint32_t addr, uint32_t r[4]) {
    asm volatile("ldmatrix.sync.aligned.m8n8.x4.shared.b16 {%0,%1,%2,%3}, [%4];"
                 : "=r"(r[0]), "=r"(r[1]), "=r"(r[2]), "=r"(r[3]) : "r"(addr));
}
__device__ __forceinline__ void mma16816(float c[4], const uint32_t a[4],
                                         uint32_t b0, uint32_t b1) {
    asm volatile("mma.sync.aligned.m16n8k16.row.col.f32.f16.f16.f32 "
                 "{%0,%1,%2,%3}, {%4,%5,%6,%7}, {%8,%9}, {%0,%1,%2,%3};"
                 : "+f"(c[0]), "+f"(c[1]), "+f"(c[2]), "+f"(c[3])
                 : "r"(a[0]), "r"(a[1]), "r"(a[2]), "r"(a[3]), "r"(b0), "r"(b1));
}
__device__ __forceinline__ float wred(float v) {
    #pragma unroll
    for (int o = 16; o > 0; o >>= 1)
        v += __shfl_xor_sync(0xFFFFFFFFu, v, o);
    return v;
}
__device__ __forceinline__ uint32_t packh2(float a, float b) {
    return (uint32_t)__half_as_ushort(__float2half_rn(a))
         | ((uint32_t)__half_as_ushort(__float2half_rn(b)) << 16);
}

// ---------------- K1: layer-1, warp per row (+ g_acc init) ----------------
__global__ __launch_bounds__(256) void k_layer1(const float* __restrict__ W1,
                                                const float* __restrict__ x,
                                                const float* __restrict__ b1) {
    if (blockIdx.x == 0 && threadIdx.x == 0) g_acc = 0.0;
    int wid  = threadIdx.x >> 5;
    int lane = threadIdx.x & 31;
    int h    = blockIdx.x * 8 + wid;
    const float4* W4 = reinterpret_cast<const float4*>(W1 + (size_t)h * D);
    const float4* x4 = reinterpret_cast<const float4*>(x);
    float dot = 0.f, r = 0.f;
    #pragma unroll
    for (int q = 0; q < 8; q++) {
        float4 w  = W4[lane + q * 32];
        float4 xv = x4[lane + q * 32];
        dot += w.x * xv.x + w.y * xv.y + w.z * xv.z + w.w * xv.w;
        r   += w.x * w.x  + w.y * w.y  + w.z * w.z  + w.w * w.w;
    }
    dot = wred(dot);
    r   = wred(r);
    if (lane == 0) {
        float u0 = tanhf(dot + b1[h]);
        float s  = 1.0f - u0 * u0;
        g_s[h]   = s;
        g_u0[h]  = u0;
        g_g[h]   = -2.0f * u0 * s * r;
    }
}

// ---------------- K_T: transpose W1 -> fp16, chunk-blocked+swizzled --------------
__global__ __launch_bounds__(256) void k_transpose(const float* __restrict__ W1) {
    __shared__ float tile[64][33];
    int i0 = blockIdx.x * 32;
    int h0 = blockIdx.y * 64;
    int t  = threadIdx.x;
    {
        int c = t & 31;
        int rbase = (t >> 5) * 8;
        #pragma unroll
        for (int q = 0; q < 8; q++)
            tile[rbase + q][c] = W1[(size_t)(h0 + rbase + q) * D + i0 + c];
    }
    __syncthreads();
    int il = t >> 3;
    int c  = t & 7;
    int i  = i0 + il;
    uint4 o;
    o.x = packh2(tile[c * 8 + 0][il], tile[c * 8 + 1][il]);
    o.y = packh2(tile[c * 8 + 2][il], tile[c * 8 + 3][il]);
    o.z = packh2(tile[c * 8 + 4][il], tile[c * 8 + 5][il]);
    o.w = packh2(tile[c * 8 + 6][il], tile[c * 8 + 7][il]);
    size_t off = ((size_t)(h0 >> 6) * D + i) * 64 + ((c ^ (i & 7)) << 3);
    *reinterpret_cast<uint4*>(g_At + off) = o;
}

// ---------------- K2: layer-2, 4 rows per block; W2t = rn(W2*s) fp16 -------------
__global__ __launch_bounds__(256) void k_layer2(const float* __restrict__ W2,
                                                const float* __restrict__ b2,
                                                const float* __restrict__ W3) {
    int j0 = blockIdx.x * 4;
    int t  = threadIdx.x;
    const float4* u4 = reinterpret_cast<const float4*>(g_u0);
    const float4* g4 = reinterpret_cast<const float4*>(g_g);
    const float4* s4 = reinterpret_cast<const float4*>(g_s);
    float z0[4]  = {0.f, 0.f, 0.f, 0.f};
    float sz2[4] = {0.f, 0.f, 0.f, 0.f};
    #pragma unroll
    for (int q = 0; q < 2; q++) {
        int u = t + q * 256;
        float4 ua = u4[u * 2], ub = u4[u * 2 + 1];
        float4 ga = g4[u * 2], gb = g4[u * 2 + 1];
        float4 sa = s4[u * 2], sb = s4[u * 2 + 1];
        #pragma unroll
        for (int r = 0; r < 4; r++) {
            int j = j0 + r;
            const float4* W4 = reinterpret_cast<const float4*>(W2 + (size_t)j * H1);
            float4 w0 = W4[u * 2];
            float4 w1 = W4[u * 2 + 1];
            z0[r]  += w0.x * ua.x + w0.y * ua.y + w0.z * ua.z + w0.w * ua.w
                    + w1.x * ub.x + w1.y * ub.y + w1.z * ub.z + w1.w * ub.w;
            sz2[r] += w0.x * ga.x + w0.y * ga.y + w0.z * ga.z + w0.w * ga.w
                    + w1.x * gb.x + w1.y * gb.y + w1.z * gb.z + w1.w * gb.w;
            uint4 o;
            o.x = packh2(w0.x * sa.x, w0.y * sa.y);
            o.y = packh2(w0.z * sa.z, w0.w * sa.w);
            o.z = packh2(w1.x * sb.x, w1.y * sb.y);
            o.w = packh2(w1.z * sb.z, w1.w * sb.w);
            size_t off = ((size_t)(u >> 3) * H2 + j) * 64 + (((u & 7) ^ (j & 7)) << 3);
            *reinterpret_cast<uint4*>(g_W2t + off) = o;
        }
    }
    #pragma unroll
    for (int r = 0; r < 4; r++) { z0[r] = wred(z0[r]); sz2[r] = wred(sz2[r]); }
    __shared__ float pz[4][8], ps[4][8];
    int wid = t >> 5, lane = t & 31;
    if (lane == 0) {
        #pragma unroll
        for (int r = 0; r < 4; r++) { pz[r][wid] = z0[r]; ps[r][wid] = sz2[r]; }
    }
    __syncthreads();
    if (t < 4) {
        float a = 0.f, b = 0.f;
        #pragma unroll
        for (int q = 0; q < 8; q++) { a += pz[t][q]; b += ps[t][q]; }
        int j = j0 + t;
        float v0 = tanhf(a + b2[j]);
        float tt = 1.0f - v0 * v0;
        float w3 = W3[j];
        atomicAdd(&g_acc, (double)(w3 * tt * b));
        g_coefQ[j] = -2.0f * w3 * v0 * tt;
    }
}

// ---------------- K3: fp16 mma.sync GEMM, 64x64 warp tile (4 warps/CTA) ----------
// z1[j,i] = sum_h rn(W2*s)[j,h] * rn(W1^T)[i,h];  acc += coefQ[j]*z1^2
// Block 128x128, BK=64, 4 warps of 64(m)x64(n). 8 LDSM -> 32 MMA per k-slice;
// barrier pair amortized over 128 MMA/warp/chunk. 3-stage bulk-copy, 2 CTA/SM.
#define BK        64
#define NCH       (H1 / BK)          // 64
#define TILE_BY   16384
#define STAGE_BY  (2 * TILE_BY)      // 32 KB
#define GEMM_SMEM (1024 + 1024 + 3 * STAGE_BY)

__global__ __launch_bounds__(128, 2) void k_gemm() {
    extern __shared__ char dyn[];
    uint32_t raw  = smem_u32(dyn);
    uint32_t base = (raw + 1023u) & ~1023u;
    char*    gen  = dyn + (base - raw);
    const uint32_t stage0 = base + 1024;

    const int t    = threadIdx.x;
    const int w    = t >> 5;         // 0..3
    const int lane = t & 31;
    const int j0   = blockIdx.x * 128;
    const int i0   = blockIdx.y * 128;

    if (t == 0) {
        MBAR_INIT(base + 0, 1);
        MBAR_INIT(base + 8, 1);
        MBAR_INIT(base + 16, 1);
    }
    __syncthreads();

    const char* srcA = (const char*)g_W2t + (size_t)j0 * 128;
    const char* srcB = (const char*)g_At  + (size_t)i0 * 128;

    auto issue = [&](int s, int kc) {
        uint32_t mb = base + 8u * (uint32_t)s;
        uint32_t db = stage0 + (uint32_t)s * STAGE_BY;
        MBAR_EXPECT(mb, (uint32_t)STAGE_BY);
        BULK_G2S(db,           srcA + (size_t)kc * H2 * 128, (uint32_t)TILE_BY, mb);
        BULK_G2S(db + TILE_BY, srcB + (size_t)kc * D  * 128, (uint32_t)TILE_BY, mb);
    };

    // warp tiling: 64(m) x 64(n); m0 = (w>>1)*64, n0 = (w&1)*64
    const int m0 = (w >> 1) * 64;
    const int n0 = (w & 1) * 64;
    const uint32_t sw   = (uint32_t)(lane & 7);
    const uint32_t rsel = (uint32_t)(lane >> 4);
    uint32_t aRow[4], bRow[4];
    #pragma unroll
    for (int mt = 0; mt < 4; mt++)
        aRow[mt] = stage0 + (uint32_t)((m0 + 16 * mt + (lane & 15)) * 128);
    #pragma unroll
    for (int bt = 0; bt < 4; bt++)
        bRow[bt] = stage0 + TILE_BY + (uint32_t)((n0 + 16 * bt + (lane & 15)) * 128);

    float acc[4][8][4];
    #pragma unroll
    for (int mt = 0; mt < 4; mt++)
        #pragma unroll
        for (int nt = 0; nt < 8; nt++)
            #pragma unroll
            for (int e = 0; e < 4; e++) acc[mt][nt][e] = 0.f;

    if (t == 0) { issue(0, 0); issue(1, 1); }

    int st = 0, ld = 2;
    uint32_t phase[3] = {0u, 0u, 0u};
    #pragma unroll 1
    for (int k = 0; k < NCH; k++) {
        __syncthreads();                       // stage 'ld' fully consumed
        if (t == 0 && k + 2 < NCH) issue(ld, k + 2);
        mbar_wait(base + 8u * (uint32_t)st, phase[st]);
        phase[st] ^= 1u;
        const uint32_t sb = (uint32_t)st * STAGE_BY;
        #pragma unroll
        for (int ks = 0; ks < 4; ks++) {
            const uint32_t off = (((2u * ks + rsel) ^ sw) << 4) + sb;
            uint32_t ah[4][4], bh[4][4];
            ldm4(aRow[0] + off, ah[0]);
            ldm4(aRow[1] + off, ah[1]);
            ldm4(aRow[2] + off, ah[2]);
            ldm4(aRow[3] + off, ah[3]);
            ldm4(bRow[0] + off, bh[0]);
            ldm4(bRow[1] + off, bh[1]);
            ldm4(bRow[2] + off, bh[2]);
            ldm4(bRow[3] + off, bh[3]);
            #pragma unroll
            for (int mt = 0; mt < 4; mt++) {
                #pragma unroll
                for (int bt = 0; bt < 4; bt++) {
                    mma16816(acc[mt][bt * 2 + 0], ah[mt], bh[bt][0], bh[bt][2]);
                    mma16816(acc[mt][bt * 2 + 1], ah[mt], bh[bt][1], bh[bt][3]);
                }
            }
        }
        st = (st == 2) ? 0 : st + 1;
        ld = (ld == 2) ? 0 : ld + 1;
    }

    // epilogue
    float part = 0.f;
    #pragma unroll
    for (int mt = 0; mt < 4; mt++) {
        int r0 = j0 + m0 + 16 * mt + (lane >> 2);
        float c0 = g_coefQ[r0];
        float c1 = g_coefQ[r0 + 8];
        float s0 = 0.f, s1 = 0.f;
        #pragma unroll
        for (int nt = 0; nt < 8; nt++) {
            s0 = fmaf(acc[mt][nt][0], acc[mt][nt][0], s0);
            s0 = fmaf(acc[mt][nt][1], acc[mt][nt][1], s0);
            s1 = fmaf(acc[mt][nt][2], acc[mt][nt][2], s1);
            s1 = fmaf(acc[mt][nt][3], acc[mt][nt][3], s1);
        }
        part = fmaf(c0, s0, part);
        part = fmaf(c1, s1, part);
    }
    part += __shfl_xor_sync(0xFFFFFFFFu, part, 16);
    part += __shfl_xor_sync(0xFFFFFFFFu, part, 8);
    part += __shfl_xor_sync(0xFFFFFFFFu, part, 4);
    part += __shfl_xor_sync(0xFFFFFFFFu, part, 2);
    part += __shfl_xor_sync(0xFFFFFFFFu, part, 1);
    __syncthreads();
    float* red = reinterpret_cast<float*>(gen);
    if (lane == 0) red[w] = part;
    __syncthreads();
    if (t == 0) {
        float s = red[0] + red[1] + red[2] + red[3];
        atomicAdd(&g_acc, (double)s);
    }
}

// ---------------- finalize ----------------
__global__ void k_final(float* __restrict__ out) { out[0] = (float)g_acc; }

// ---------------- launch ----------------
extern "C" void kernel_launch(void* const* d_in, const int* in_sizes, int n_in,
                              void* d_out, int out_size) {
    const float* x  = (const float*)d_in[0];
    const float* W1 = (const float*)d_in[1];
    const float* b1 = (const float*)d_in[2];
    const float* W2 = (const float*)d_in[3];
    const float* b2 = (const float*)d_in[4];
    const float* W3 = (const float*)d_in[5];
    float* out = (float*)d_out;

    cudaFuncSetAttribute(k_gemm, cudaFuncAttributeMaxDynamicSharedMemorySize, GEMM_SMEM);

    k_layer1<<<H1 / 8, 256>>>(W1, x, b1);
    k_transpose<<<dim3(D / 32, H1 / 64), 256>>>(W1);
    k_layer2<<<H2 / 4, 256>>>(W2, b2, W3);
    k_gemm<<<dim3(H2 / 128, D / 128), 128, GEMM_SMEM>>>();
    k_final<<<1, 1>>>(out);
}

// round 17
// speedup vs baseline: 1.1287x; 1.0012x over previous
#include <cuda_runtime.h>
#include <cuda_fp16.h>
#include <math.h>
#include <stdint.h>

#define D   1024
#define H1  4096
#define H2  4096

// ---------------- scratch (static device globals; no allocation) ----------------
__device__ float   g_dot[H1];                 // partial W1.x   (zeroed by k_act for replays)
__device__ float   g_r[H1];                   // partial ||W1||^2
__device__ float   g_s[H1];
__device__ float   g_u0[H1];
__device__ float   g_g[H1];
__device__ float   g_coefQ[H2];
__device__ double  g_acc;
__device__ unsigned g_done;                   // gemm completion counter
__device__ __half  g_W2t[(size_t)H2 * H1];    // rn(W2[j,h]*s[h]) chunk-blocked  (32 MB)
__device__ __half  g_At[(size_t)D * H1];      // rn(W1^T) chunk-blocked          (8 MB)

// ---------------- portable PTX helpers (sm_90 baseline, no 'a' features) --------
__device__ __forceinline__ uint32_t smem_u32(const void* p) {
    uint32_t a;
    asm("{ .reg .u64 t; cvta.to.shared.u64 t, %1; cvt.u32.u64 %0, t; }" : "=r"(a) : "l"(p));
    return a;
}
#define MBAR_INIT(mb, c) asm volatile("mbarrier.init.shared.b64 [%0], %1;" :: "r"(mb), "r"(c) : "memory")
#define MBAR_EXPECT(mb, n) asm volatile("mbarrier.arrive.expect_tx.shared.b64 _, [%0], %1;" :: "r"(mb), "r"(n) : "memory")
#define BULK_G2S(dst, src, n, mb) \
    asm volatile("cp.async.bulk.shared::cluster.global.mbarrier::complete_tx::bytes [%0], [%1], %2, [%3];" \
                 :: "r"(dst), "l"(src), "r"(n), "r"(mb) : "memory")
__device__ __forceinline__ void mbar_wait(uint32_t mb, uint32_t parity) {
    uint32_t done;
    asm volatile("{ .reg .pred p; mbarrier.try_wait.parity.acquire.cta.shared::cta.b64 p, [%1], %2; selp.b32 %0, 1, 0, p; }"
                 : "=r"(done) : "r"(mb), "r"(parity) : "memory");
    if (!done) {
        asm volatile("{ .reg .pred P1; WL%=: mbarrier.try_wait.parity.acquire.cta.shared::cta.b64 P1, [%0], %1, 0x989680; @P1 bra.uni WD%=; bra.uni WL%=; WD%=: }"
                     :: "r"(mb), "r"(parity) : "memory");
    }
}
__device__ __forceinline__ void ldm4(uint32_t addr, uint32_t r[4]) {
    asm volatile("ldmatrix.sync.aligned.m8n8.x4.shared.b16 {%0,%1,%2,%3}, [%4];"
                 : "=r"(r[0]), "=r"(r[1]), "=r"(r[2]), "=r"(r[3]) : "r"(addr));
}
__device__ __forceinline__ void mma16816(float c[4], const uint32_t a[4],
                                         uint32_t b0, uint32_t b1) {
    asm volatile("mma.sync.aligned.m16n8k16.row.col.f32.f16.f16.f32 "
                 "{%0,%1,%2,%3}, {%4,%5,%6,%7}, {%8,%9}, {%0,%1,%2,%3};"
                 : "+f"(c[0]), "+f"(c[1]), "+f"(c[2]), "+f"(c[3])
                 : "r"(a[0]), "r"(a[1]), "r"(a[2]), "r"(a[3]), "r"(b0), "r"(b1));
}
__device__ __forceinline__ float wred(float v) {
    #pragma unroll
    for (int o = 16; o > 0; o >>= 1)
        v += __shfl_xor_sync(0xFFFFFFFFu, v, o);
    return v;
}
__device__ __forceinline__ uint32_t packh2(float a, float b) {
    return (uint32_t)__half_as_ushort(__float2half_rn(a))
         | ((uint32_t)__half_as_ushort(__float2half_rn(b)) << 16);
}

// ---------------- K_prep: transpose W1 -> fp16 At + partial dot/norm atomics -----
__global__ __launch_bounds__(256) void k_prep(const float* __restrict__ W1,
                                              const float* __restrict__ x) {
    __shared__ float tile[64][33];
    __shared__ float xs[32];
    int i0 = blockIdx.x * 32;
    int h0 = blockIdx.y * 64;
    int t  = threadIdx.x;
    if (t < 32) xs[t] = x[i0 + t];
    {
        int c = t & 31;
        int rbase = (t >> 5) * 8;
        #pragma unroll
        for (int q = 0; q < 8; q++)
            tile[rbase + q][c] = W1[(size_t)(h0 + rbase + q) * D + i0 + c];
    }
    __syncthreads();
    // transposed fp16 write (chunk-blocked + swizzled), identical bits to R16
    {
        int il = t >> 3;
        int c  = t & 7;
        int i  = i0 + il;
        uint4 o;
        o.x = packh2(tile[c * 8 + 0][il], tile[c * 8 + 1][il]);
        o.y = packh2(tile[c * 8 + 2][il], tile[c * 8 + 3][il]);
        o.z = packh2(tile[c * 8 + 4][il], tile[c * 8 + 5][il]);
        o.w = packh2(tile[c * 8 + 6][il], tile[c * 8 + 7][il]);
        size_t off = ((size_t)(h0 >> 6) * D + i) * 64 + ((c ^ (i & 7)) << 3);
        *reinterpret_cast<uint4*>(g_At + off) = o;
    }
    // partial layer-1 reductions for this i-slab (threads 0..63, one h-row each)
    if (t < 64) {
        float pd = 0.f, pr = 0.f;
        #pragma unroll 8
        for (int il = 0; il < 32; il++) {
            float wv = tile[t][il];
            pd = fmaf(wv, xs[il], pd);
            pr = fmaf(wv, wv, pr);
        }
        atomicAdd(&g_dot[h0 + t], pd);
        atomicAdd(&g_r[h0 + t], pr);
    }
}

// ---------------- K_act: finish layer-1 activations; reset partials + g_acc ------
__global__ __launch_bounds__(256) void k_act(const float* __restrict__ b1) {
    int h = blockIdx.x * 256 + threadIdx.x;
    float dot = g_dot[h];
    float r   = g_r[h];
    float u0  = tanhf(dot + b1[h]);
    float s   = 1.0f - u0 * u0;
    g_u0[h] = u0;
    g_s[h]  = s;
    g_g[h]  = -2.0f * u0 * s * r;
    g_dot[h] = 0.f;          // ready for next replay
    g_r[h]   = 0.f;
    if (h == 0) { g_acc = 0.0; g_done = 0u; }
}

// ---------------- K2: layer-2, 4 rows per block; W2t = rn(W2*s) fp16 -------------
__global__ __launch_bounds__(256) void k_layer2(const float* __restrict__ W2,
                                                const float* __restrict__ b2,
                                                const float* __restrict__ W3) {
    int j0 = blockIdx.x * 4;
    int t  = threadIdx.x;
    const float4* u4 = reinterpret_cast<const float4*>(g_u0);
    const float4* g4 = reinterpret_cast<const float4*>(g_g);
    const float4* s4 = reinterpret_cast<const float4*>(g_s);
    float z0[4]  = {0.f, 0.f, 0.f, 0.f};
    float sz2[4] = {0.f, 0.f, 0.f, 0.f};
    #pragma unroll
    for (int q = 0; q < 2; q++) {
        int u = t + q * 256;
        float4 ua = u4[u * 2], ub = u4[u * 2 + 1];
        float4 ga = g4[u * 2], gb = g4[u * 2 + 1];
        float4 sa = s4[u * 2], sb = s4[u * 2 + 1];
        #pragma unroll
        for (int r = 0; r < 4; r++) {
            int j = j0 + r;
            const float4* W4 = reinterpret_cast<const float4*>(W2 + (size_t)j * H1);
            float4 w0 = W4[u * 2];
            float4 w1 = W4[u * 2 + 1];
            z0[r]  += w0.x * ua.x + w0.y * ua.y + w0.z * ua.z + w0.w * ua.w
                    + w1.x * ub.x + w1.y * ub.y + w1.z * ub.z + w1.w * ub.w;
            sz2[r] += w0.x * ga.x + w0.y * ga.y + w0.z * ga.z + w0.w * ga.w
                    + w1.x * gb.x + w1.y * gb.y + w1.z * gb.z + w1.w * gb.w;
            uint4 o;
            o.x = packh2(w0.x * sa.x, w0.y * sa.y);
            o.y = packh2(w0.z * sa.z, w0.w * sa.w);
            o.z = packh2(w1.x * sb.x, w1.y * sb.y);
            o.w = packh2(w1.z * sb.z, w1.w * sb.w);
            size_t off = ((size_t)(u >> 3) * H2 + j) * 64 + (((u & 7) ^ (j & 7)) << 3);
            *reinterpret_cast<uint4*>(g_W2t + off) = o;
        }
    }
    #pragma unroll
    for (int r = 0; r < 4; r++) { z0[r] = wred(z0[r]); sz2[r] = wred(sz2[r]); }
    __shared__ float pz[4][8], ps[4][8];
    int wid = t >> 5, lane = t & 31;
    if (lane == 0) {
        #pragma unroll
        for (int r = 0; r < 4; r++) { pz[r][wid] = z0[r]; ps[r][wid] = sz2[r]; }
    }
    __syncthreads();
    if (t < 4) {
        float a = 0.f, b = 0.f;
        #pragma unroll
        for (int q = 0; q < 8; q++) { a += pz[t][q]; b += ps[t][q]; }
        int j = j0 + t;
        float v0 = tanhf(a + b2[j]);
        float tt = 1.0f - v0 * v0;
        float w3 = W3[j];
        atomicAdd(&g_acc, (double)(w3 * tt * b));
        g_coefQ[j] = -2.0f * w3 * v0 * tt;
    }
}

// ---------------- K3: fp16 mma.sync GEMM (R16 shape) + fused finalize ------------
// Block 128x128, BK=64, 4 warps of 64(m)x64(n), 3-stage bulk-copy, 2 CTA/SM.
// Last block (completion counter) writes out[0].
#define BK        64
#define NCH       (H1 / BK)          // 64
#define TILE_BY   16384
#define STAGE_BY  (2 * TILE_BY)      // 32 KB
#define GEMM_SMEM (1024 + 1024 + 3 * STAGE_BY)
#define GEMM_BLOCKS ((H2 / 128) * (D / 128))   // 256

__global__ __launch_bounds__(128, 2) void k_gemm(float* __restrict__ out) {
    extern __shared__ char dyn[];
    uint32_t raw  = smem_u32(dyn);
    uint32_t base = (raw + 1023u) & ~1023u;
    char*    gen  = dyn + (base - raw);
    const uint32_t stage0 = base + 1024;

    const int t    = threadIdx.x;
    const int w    = t >> 5;         // 0..3
    const int lane = t & 31;
    const int j0   = blockIdx.x * 128;
    const int i0   = blockIdx.y * 128;

    if (t == 0) {
        MBAR_INIT(base + 0, 1);
        MBAR_INIT(base + 8, 1);
        MBAR_INIT(base + 16, 1);
    }
    __syncthreads();

    const char* srcA = (const char*)g_W2t + (size_t)j0 * 128;
    const char* srcB = (const char*)g_At  + (size_t)i0 * 128;

    auto issue = [&](int s, int kc) {
        uint32_t mb = base + 8u * (uint32_t)s;
        uint32_t db = stage0 + (uint32_t)s * STAGE_BY;
        MBAR_EXPECT(mb, (uint32_t)STAGE_BY);
        BULK_G2S(db,           srcA + (size_t)kc * H2 * 128, (uint32_t)TILE_BY, mb);
        BULK_G2S(db + TILE_BY, srcB + (size_t)kc * D  * 128, (uint32_t)TILE_BY, mb);
    };

    // warp tiling: 64(m) x 64(n)
    const int m0 = (w >> 1) * 64;
    const int n0 = (w & 1) * 64;
    const uint32_t sw   = (uint32_t)(lane & 7);
    const uint32_t rsel = (uint32_t)(lane >> 4);
    uint32_t aRow[4], bRow[4];
    #pragma unroll
    for (int mt = 0; mt < 4; mt++)
        aRow[mt] = stage0 + (uint32_t)((m0 + 16 * mt + (lane & 15)) * 128);
    #pragma unroll
    for (int bt = 0; bt < 4; bt++)
        bRow[bt] = stage0 + TILE_BY + (uint32_t)((n0 + 16 * bt + (lane & 15)) * 128);

    float acc[4][8][4];
    #pragma unroll
    for (int mt = 0; mt < 4; mt++)
        #pragma unroll
        for (int nt = 0; nt < 8; nt++)
            #pragma unroll
            for (int e = 0; e < 4; e++) acc[mt][nt][e] = 0.f;

    if (t == 0) { issue(0, 0); issue(1, 1); }

    int st = 0, ld = 2;
    uint32_t phase[3] = {0u, 0u, 0u};
    #pragma unroll 1
    for (int k = 0; k < NCH; k++) {
        __syncthreads();                       // stage 'ld' fully consumed
        if (t == 0 && k + 2 < NCH) issue(ld, k + 2);
        mbar_wait(base + 8u * (uint32_t)st, phase[st]);
        phase[st] ^= 1u;
        const uint32_t sb = (uint32_t)st * STAGE_BY;
        #pragma unroll
        for (int ks = 0; ks < 4; ks++) {
            const uint32_t off = (((2u * ks + rsel) ^ sw) << 4) + sb;
            uint32_t ah[4][4], bh[4][4];
            ldm4(aRow[0] + off, ah[0]);
            ldm4(aRow[1] + off, ah[1]);
            ldm4(aRow[2] + off, ah[2]);
            ldm4(aRow[3] + off, ah[3]);
            ldm4(bRow[0] + off, bh[0]);
            ldm4(bRow[1] + off, bh[1]);
            ldm4(bRow[2] + off, bh[2]);
            ldm4(bRow[3] + off, bh[3]);
            #pragma unroll
            for (int mt = 0; mt < 4; mt++) {
                #pragma unroll
                for (int bt = 0; bt < 4; bt++) {
                    mma16816(acc[mt][bt * 2 + 0], ah[mt], bh[bt][0], bh[bt][2]);
                    mma16816(acc[mt][bt * 2 + 1], ah[mt], bh[bt][1], bh[bt][3]);
                }
            }
        }
        st = (st == 2) ? 0 : st + 1;
        ld = (ld == 2) ? 0 : ld + 1;
    }

    // epilogue
    float part = 0.f;
    #pragma unroll
    for (int mt = 0; mt < 4; mt++) {
        int r0 = j0 + m0 + 16 * mt + (lane >> 2);
        float c0 = g_coefQ[r0];
        float c1 = g_coefQ[r0 + 8];
        float s0 = 0.f, s1 = 0.f;
        #pragma unroll
        for (int nt = 0; nt < 8; nt++) {
            s0 = fmaf(acc[mt][nt][0], acc[mt][nt][0], s0);
            s0 = fmaf(acc[mt][nt][1], acc[mt][nt][1], s0);
            s1 = fmaf(acc[mt][nt][2], acc[mt][nt][2], s1);
            s1 = fmaf(acc[mt][nt][3], acc[mt][nt][3], s1);
        }
        part = fmaf(c0, s0, part);
        part = fmaf(c1, s1, part);
    }
    part += __shfl_xor_sync(0xFFFFFFFFu, part, 16);
    part += __shfl_xor_sync(0xFFFFFFFFu, part, 8);
    part += __shfl_xor_sync(0xFFFFFFFFu, part, 4);
    part += __shfl_xor_sync(0xFFFFFFFFu, part, 2);
    part += __shfl_xor_sync(0xFFFFFFFFu, part, 1);
    __syncthreads();
    float* red = reinterpret_cast<float*>(gen);
    if (lane == 0) red[w] = part;
    __syncthreads();
    if (t == 0) {
        float s = red[0] + red[1] + red[2] + red[3];
        atomicAdd(&g_acc, (double)s);
        __threadfence();
        unsigned old = atomicAdd(&g_done, 1u);
        if (old == GEMM_BLOCKS - 1) {
            out[0] = (float)g_acc;
            g_done = 0u;             // reset for next replay (k_act also resets)
        }
    }
}

// ---------------- launch ----------------
extern "C" void kernel_launch(void* const* d_in, const int* in_sizes, int n_in,
                              void* d_out, int out_size) {
    const float* x  = (const float*)d_in[0];
    const float* W1 = (const float*)d_in[1];
    const float* b1 = (const float*)d_in[2];
    const float* W2 = (const float*)d_in[3];
    const float* b2 = (const float*)d_in[4];
    const float* W3 = (const float*)d_in[5];
    float* out = (float*)d_out;

    cudaFuncSetAttribute(k_gemm, cudaFuncAttributeMaxDynamicSharedMemorySize, GEMM_SMEM);

    k_prep<<<dim3(D / 32, H1 / 64), 256>>>(W1, x);
    k_act<<<H1 / 256, 256>>>(b1);
    k_layer2<<<H2 / 4, 256>>>(W2, b2, W3);
    k_gemm<<<dim3(H2 / 128, D / 128), 128, GEMM_SMEM>>>(out);
}